// round 9
// baseline (speedup 1.0000x reference)
#include <cuda_runtime.h>
#include <cuda_bf16.h>
#include <math.h>

// Problem dims (fixed by dataset)
#define BB 64
#define SS 512
#define HH 768
#define LL 9

#define SPLIT 4                 // chunks per token (lanes)
#define HC (HH / SPLIT)         // 192 features per chunk
#define F4C (HC / 4)            // 48 float4 per chunk
#define WREG (HC * 8 + 4)       // main W region stride (floats): 1540, mod32=4
#define W8REG (HC + 4)          // w8 quad region stride (floats): 196, mod32=4

// Scratch (no device allocations allowed)
__device__ int g_cnt[BB];        // valid count per batch
__device__ int g_src[BB * SS];   // per-batch: src token index for dest d

// ---------------------------------------------------------------------------
// Kernel 1: per-batch scan of valid_mask -> src map + counts.
// One block (512 threads) per batch row. No fill (main handles all output).
// ---------------------------------------------------------------------------
__global__ __launch_bounds__(512) void scan_kernel(const int* __restrict__ mask) {
    int b = blockIdx.x;
    int s = threadIdx.x;
    int m = (mask[b * SS + s] == 1) ? 1 : 0;

    __shared__ int wsum[16];
    int lane = s & 31, wid = s >> 5;
    int v = m;
#pragma unroll
    for (int o = 1; o < 32; o <<= 1) {
        int t = __shfl_up_sync(0xffffffffu, v, o);
        if (lane >= o) v += t;
    }
    if (lane == 31) wsum[wid] = v;
    __syncthreads();
    if (wid == 0) {
        int x = (lane < 16) ? wsum[lane] : 0;
#pragma unroll
        for (int o = 1; o < 16; o <<= 1) {
            int t = __shfl_up_sync(0xffffffffu, x, o);
            if (lane >= o) x += t;
        }
        if (lane < 16) wsum[lane] = x;
    }
    __syncthreads();
    int incl = v + (wid ? wsum[wid - 1] : 0);
    if (m) g_src[b * SS + (incl - 1)] = s;
    if (s == SS - 1) g_cnt[b] = incl;
}

// ---------------------------------------------------------------------------
// Kernel 2: main compute + tail fill. Warp = 16 work items: 8 token-lanes x
// 4 chunk-lanes; each lane handles TWO tokens sharing the W LDS loads (18
// FMAs per W row load). Batch mapping via 6-step binary search over the
// shared prefix array (replaces the build kernel). Tail slots (invalid
// destinations) written with the constant softmax(bias) at the end
// (replaces the fill kernel).
// ---------------------------------------------------------------------------
#define NBLK 296

__global__ __launch_bounds__(256, 2) void main_kernel(const float* __restrict__ seq,
                                                      const float* __restrict__ W,
                                                      const float* __restrict__ bias,
                                                      float* __restrict__ out) {
    __shared__ float Ws[SPLIT * WREG];    // cols 0..7, 8 floats/row
    __shared__ float W8s[SPLIT * W8REG];  // col 8, packed 4 rows per float4
    __shared__ float Bs[LL];
    __shared__ int pref[BB + 1];          // pref[b] = sum of cnt[0..b-1]

    int tid = threadIdx.x;
    if (tid < LL) Bs[tid] = bias[tid];
    for (int i = tid; i < SPLIT * WREG; i += 256) {
        int c = i / WREG, r = i % WREG;
        float val = 0.f;
        if (r < HC * 8) {
            int j = r / 8, col = r % 8;
            val = W[(c * HC + j) * LL + col];
        }
        Ws[i] = val;
    }
    for (int i = tid; i < SPLIT * W8REG; i += 256) {
        int c = i / W8REG, r = i % W8REG;
        float val = 0.f;
        if (r < HC) val = W[(c * HC + r) * LL + 8];
        W8s[i] = val;
    }
    // prefix over batch counts (single warp, serial-ish but tiny)
    if (tid == 0) {
        int acc = 0;
#pragma unroll
        for (int i = 0; i < BB; i++) { pref[i] = acc; acc += g_cnt[i]; }
        pref[BB] = acc;
    }
    __syncthreads();

    int total = pref[BB];
    int n_sg = (total + 15) >> 4;   // supergroups of 16 work items

    int wid = tid >> 5, lane = tid & 31;
    int t_in = lane >> 2;   // token-lane 0..7
    int c    = lane & 3;    // chunk 0..3
    int wbase  = c * WREG;
    int w8base = c * W8REG;

    int warp_g = blockIdx.x * 8 + wid;
    int nwarps = NBLK * 8;

    for (int sg = warp_g; sg < n_sg; sg += nwarps) {
        int i1 = sg * 16 + t_in;
        int i2 = i1 + 8;
        bool a1 = i1 < total;
        bool a2 = i2 < total;
        int q1 = a1 ? i1 : 0;
        int q2 = a2 ? i2 : 0;

        // batch lookup: largest b with pref[b] <= i
        int b1 = 0, b2 = 0;
#pragma unroll
        for (int st = 32; st >= 1; st >>= 1) {
            int m1 = b1 + st, m2 = b2 + st;
            if (m1 <= BB - 1 && pref[m1] <= q1) b1 = m1;
            if (m2 <= BB - 1 && pref[m2] <= q2) b2 = m2;
        }
        int d1 = q1 - pref[b1];
        int d2 = q2 - pref[b2];
        int s1 = g_src[b1 * SS + d1];
        int s2 = g_src[b2 * SS + d2];

        const float4* xp1 = (const float4*)(seq + (size_t)(b1 * SS + s1) * HH) + c * F4C;
        const float4* xp2 = (const float4*)(seq + (size_t)(b2 * SS + s2) * HH) + c * F4C;

        float acc1[LL], acc2[LL];
#pragma unroll
        for (int l = 0; l < LL; l++) { acc1[l] = 0.f; acc2[l] = 0.f; }

        // stage = 2 float4 = 8 rows; 24 stages, double-buffered
        float4 A1[2], A2[2], B1[2], B2[2];

#define CONSUME(X1, X2, ST)                                                    \
        {                                                                      \
            _Pragma("unroll") for (int k = 0; k < 2; k++) {                    \
                int qg = (ST) * 2 + k;          /* quad-group index (4 rows) */\
                float4 w8q = *(const float4*)&W8s[w8base + qg * 4];            \
                float4 xv1 = X1[k];                                            \
                float4 xv2 = X2[k];                                            \
                float xs1_[4] = {xv1.x, xv1.y, xv1.z, xv1.w};                  \
                float xs2_[4] = {xv2.x, xv2.y, xv2.z, xv2.w};                  \
                float w8_[4] = {w8q.x, w8q.y, w8q.z, w8q.w};                   \
                _Pragma("unroll") for (int j = 0; j < 4; j++) {                \
                    int row = qg * 4 + j;                                      \
                    const float4* wr = (const float4*)&Ws[wbase + row * 8];    \
                    float4 w0 = wr[0];                                         \
                    float4 w1 = wr[1];                                         \
                    float xs1 = xs1_[j], xs2 = xs2_[j], w8 = w8_[j];           \
                    acc1[0] = fmaf(xs1, w0.x, acc1[0]);                        \
                    acc2[0] = fmaf(xs2, w0.x, acc2[0]);                        \
                    acc1[1] = fmaf(xs1, w0.y, acc1[1]);                        \
                    acc2[1] = fmaf(xs2, w0.y, acc2[1]);                        \
                    acc1[2] = fmaf(xs1, w0.z, acc1[2]);                        \
                    acc2[2] = fmaf(xs2, w0.z, acc2[2]);                        \
                    acc1[3] = fmaf(xs1, w0.w, acc1[3]);                        \
                    acc2[3] = fmaf(xs2, w0.w, acc2[3]);                        \
                    acc1[4] = fmaf(xs1, w1.x, acc1[4]);                        \
                    acc2[4] = fmaf(xs2, w1.x, acc2[4]);                        \
                    acc1[5] = fmaf(xs1, w1.y, acc1[5]);                        \
                    acc2[5] = fmaf(xs2, w1.y, acc2[5]);                        \
                    acc1[6] = fmaf(xs1, w1.z, acc1[6]);                        \
                    acc2[6] = fmaf(xs2, w1.z, acc2[6]);                        \
                    acc1[7] = fmaf(xs1, w1.w, acc1[7]);                        \
                    acc2[7] = fmaf(xs2, w1.w, acc2[7]);                        \
                    acc1[8] = fmaf(xs1, w8, acc1[8]);                          \
                    acc2[8] = fmaf(xs2, w8, acc2[8]);                          \
                }                                                              \
            }                                                                  \
        }

#pragma unroll
        for (int k = 0; k < 2; k++) { A1[k] = xp1[k]; A2[k] = xp2[k]; }
#pragma unroll
        for (int st = 0; st < 24; st += 2) {
#pragma unroll
            for (int k = 0; k < 2; k++) {
                B1[k] = xp1[(st + 1) * 2 + k];
                B2[k] = xp2[(st + 1) * 2 + k];
            }
            CONSUME(A1, A2, st);
            if (st + 2 < 24) {
#pragma unroll
                for (int k = 0; k < 2; k++) {
                    A1[k] = xp1[(st + 2) * 2 + k];
                    A2[k] = xp2[(st + 2) * 2 + k];
                }
            }
            CONSUME(B1, B2, st + 1);
        }
#undef CONSUME

        // reduce over the 4 chunk lanes (xor 1, 2); all lanes end with full sums
#pragma unroll
        for (int o = 1; o <= 2; o <<= 1) {
#pragma unroll
            for (int l = 0; l < LL; l++) {
                acc1[l] += __shfl_xor_sync(0xffffffffu, acc1[l], o);
                acc2[l] += __shfl_xor_sync(0xffffffffu, acc2[l], o);
            }
        }

        // lane c==0 finalizes token1, lane c==1 finalizes token2
        bool doit = (c == 0) ? a1 : ((c == 1) ? a2 : false);
        if (doit) {
            float v[LL];
            int slot;
            if (c == 0) {
#pragma unroll
                for (int l = 0; l < LL; l++) v[l] = acc1[l] + Bs[l];
                slot = b1 * SS + d1;
            } else {
#pragma unroll
                for (int l = 0; l < LL; l++) v[l] = acc2[l] + Bs[l];
                slot = b2 * SS + d2;
            }
            float m = v[0];
#pragma unroll
            for (int l = 1; l < LL; l++) m = fmaxf(m, v[l]);
            float sum = 0.f;
#pragma unroll
            for (int l = 0; l < LL; l++) { v[l] = __expf(v[l] - m); sum += v[l]; }
            float r = 1.f / sum;
            float* op = out + (size_t)slot * LL;
#pragma unroll
            for (int l = 0; l < LL; l++) op[l] = v[l] * r;
        }
    }

    // ---- tail fill: invalid dest slots get softmax(bias) constant ----
    int n_tail = BB * SS - total;
    if (n_tail > 0) {
        float bv[LL];
#pragma unroll
        for (int l = 0; l < LL; l++) bv[l] = Bs[l];
        float mx = bv[0];
#pragma unroll
        for (int l = 1; l < LL; l++) mx = fmaxf(mx, bv[l]);
        float sum = 0.f;
#pragma unroll
        for (int l = 0; l < LL; l++) { bv[l] = __expf(bv[l] - mx); sum += bv[l]; }
        float r = 1.f / sum;
#pragma unroll
        for (int l = 0; l < LL; l++) bv[l] *= r;

        int gtid = blockIdx.x * 256 + tid;
        int gsz = NBLK * 256;
        for (int j = gtid; j < n_tail; j += gsz) {
            // largest b with tpref[b] <= j, tpref[b] = b*SS - pref[b]
            int b = 0;
#pragma unroll
            for (int st = 32; st >= 1; st >>= 1) {
                int m = b + st;
                if (m <= BB - 1 && (m * SS - pref[m]) <= j) b = m;
            }
            int d = (pref[b + 1] - pref[b]) + (j - (b * SS - pref[b]));
            float* op = out + (size_t)(b * SS + d) * LL;
#pragma unroll
            for (int l = 0; l < LL; l++) op[l] = bv[l];
        }
    }
}

// ---------------------------------------------------------------------------
extern "C" void kernel_launch(void* const* d_in, const int* in_sizes, int n_in,
                              void* d_out, int out_size) {
    const float* seq  = (const float*)d_in[0];   // [64,512,768] f32
    const int*   mask = (const int*)d_in[1];     // [64,512] i32
    const float* W    = (const float*)d_in[2];   // [768,9] f32
    const float* bias = (const float*)d_in[3];   // [9] f32
    float* out = (float*)d_out;                  // [64,512,9] f32

    scan_kernel<<<BB, SS>>>(mask);
    main_kernel<<<NBLK, 256>>>(seq, W, bias, out);
}

// round 10
// speedup vs baseline: 1.7399x; 1.7399x over previous
#include <cuda_runtime.h>
#include <cuda_bf16.h>
#include <math.h>

// Problem dims (fixed by dataset)
#define BB 64
#define SS 512
#define HH 768
#define LL 9

#define SPLIT 8                 // chunk lanes per token
#define TL 4                    // token lanes (8 tokens per warp: 4 lanes x 2 tokens)
#define HC (HH / SPLIT)         // 96 features per chunk
#define F4C (HC / 4)            // 24 float4 per chunk
#define WREG (HC * 8 + 4)       // 772 floats, mod 32 = 4 -> bank rotation
#define W8REG (HC + 4)          // 100 floats, mod 32 = 4

// Scratch (no device allocations allowed)
__device__ int g_cnt[BB];        // valid count per batch
__device__ int g_src[BB * SS];   // per-batch: src token index for dest d
__device__ int g_items[BB * SS]; // global work list: b<<18 | d<<9 | s

// ---------------------------------------------------------------------------
// Kernel 1: per-batch scan of valid_mask -> src map + counts, AND fill the
// whole output with softmax(bias). One block (512 threads) per batch row.
// ---------------------------------------------------------------------------
__global__ __launch_bounds__(512) void scan_fill_kernel(const int* __restrict__ mask,
                                                        const float* __restrict__ bias,
                                                        float* __restrict__ out) {
    int b = blockIdx.x;
    int s = threadIdx.x;
    int m = (mask[b * SS + s] == 1) ? 1 : 0;

    __shared__ int wsum[16];
    int lane = s & 31, wid = s >> 5;
    int v = m;
#pragma unroll
    for (int o = 1; o < 32; o <<= 1) {
        int t = __shfl_up_sync(0xffffffffu, v, o);
        if (lane >= o) v += t;
    }
    if (lane == 31) wsum[wid] = v;
    __syncthreads();
    if (wid == 0) {
        int x = (lane < 16) ? wsum[lane] : 0;
#pragma unroll
        for (int o = 1; o < 16; o <<= 1) {
            int t = __shfl_up_sync(0xffffffffu, x, o);
            if (lane >= o) x += t;
        }
        if (lane < 16) wsum[lane] = x;
    }
    __syncthreads();
    int incl = v + (wid ? wsum[wid - 1] : 0);
    if (m) g_src[b * SS + (incl - 1)] = s;
    if (s == SS - 1) g_cnt[b] = incl;

    // fill: softmax(bias) constant into every slot of this batch row
    float bv[LL];
#pragma unroll
    for (int l = 0; l < LL; l++) bv[l] = __ldg(bias + l);
    float mx = bv[0];
#pragma unroll
    for (int l = 1; l < LL; l++) mx = fmaxf(mx, bv[l]);
    float sum = 0.f;
#pragma unroll
    for (int l = 0; l < LL; l++) { bv[l] = __expf(bv[l] - mx); sum += bv[l]; }
    float r = 1.f / sum;
    float* op = out + (size_t)(b * SS + s) * LL;
#pragma unroll
    for (int l = 0; l < LL; l++) op[l] = bv[l] * r;
}

// ---------------------------------------------------------------------------
// Kernel 2: build globally-compacted work list (perfect load balance)
// ---------------------------------------------------------------------------
__global__ __launch_bounds__(512) void build_kernel() {
    int b = blockIdx.x;
    int d = threadIdx.x;
    __shared__ int scnt[BB];
    __shared__ int soff;
    if (d < BB) scnt[d] = g_cnt[d];
    __syncthreads();
    if (d == 0) {
        int o = 0;
#pragma unroll
        for (int i = 0; i < BB; i++) o += (i < b) ? scnt[i] : 0;
        soff = o;
    }
    __syncthreads();
    if (d < scnt[b]) {
        g_items[soff + d] = (b << 18) | (d << 9) | g_src[b * SS + d];
    }
}

// ---------------------------------------------------------------------------
// Kernel 3: main compute. Warp = 8 work items: 4 token-lanes x 8 chunk-lanes,
// each lane handles TWO tokens that SHARE the W shared-memory loads (18 FMAs
// per W row load). 8 tokens/warp -> ~2048 busy warps (~3.5/SMSP) for latency
// hiding. Small double-buffer (1 float4 per token) keeps regs low.
// Bank-rotated W regions: conflict-free LDS with 4-way broadcast.
// ---------------------------------------------------------------------------
#define NBLK 296

__global__ __launch_bounds__(256, 2) void main_kernel(const float* __restrict__ seq,
                                                      const float* __restrict__ W,
                                                      const float* __restrict__ bias,
                                                      float* __restrict__ out) {
    __shared__ float Ws[SPLIT * WREG];    // cols 0..7, 8 floats/row  (~24.7 KB)
    __shared__ float W8s[SPLIT * W8REG];  // col 8, quad-packed       (~3.2 KB)
    __shared__ float Bs[LL];
    __shared__ int s_total;

    int tid = threadIdx.x;
    if (tid == 0) s_total = 0;
    if (tid < LL) Bs[tid] = bias[tid];
    for (int i = tid; i < SPLIT * WREG; i += 256) {
        int c = i / WREG, r = i % WREG;
        float val = 0.f;
        if (r < HC * 8) {
            int j = r / 8, col = r % 8;
            val = W[(c * HC + j) * LL + col];
        }
        Ws[i] = val;
    }
    for (int i = tid; i < SPLIT * W8REG; i += 256) {
        int c = i / W8REG, r = i % W8REG;
        float val = 0.f;
        if (r < HC) val = W[(c * HC + r) * LL + 8];
        W8s[i] = val;
    }
    __syncthreads();
    if (tid < BB) atomicAdd(&s_total, g_cnt[tid]);
    __syncthreads();

    int total = s_total;
    int n_sg = (total + 7) >> 3;   // supergroups of 8 work items

    int wid = tid >> 5, lane = tid & 31;
    int t_in = lane >> 3;   // token-lane 0..3
    int c    = lane & 7;    // chunk 0..7
    int wbase  = c * WREG;
    int w8base = c * W8REG;

    int warp_g = blockIdx.x * 8 + wid;
    int nwarps = NBLK * 8;

    for (int sg = warp_g; sg < n_sg; sg += nwarps) {
        int i1 = sg * 8 + t_in;
        int i2 = i1 + 4;
        bool a1 = i1 < total;
        bool a2 = i2 < total;
        int item1 = a1 ? g_items[i1] : 0;
        int item2 = a2 ? g_items[i2] : 0;
        int b1 = item1 >> 18, d1 = (item1 >> 9) & 511, s1 = item1 & 511;
        int b2 = item2 >> 18, d2 = (item2 >> 9) & 511, s2 = item2 & 511;

        const float4* xp1 = (const float4*)(seq + (size_t)(b1 * SS + s1) * HH) + c * F4C;
        const float4* xp2 = (const float4*)(seq + (size_t)(b2 * SS + s2) * HH) + c * F4C;

        float acc1[LL], acc2[LL];
#pragma unroll
        for (int l = 0; l < LL; l++) { acc1[l] = 0.f; acc2[l] = 0.f; }

        // stage = 1 float4 per token = 4 rows; 24 stages, double-buffered
        float4 A1, A2, B1, B2;

#define CONSUME(X1, X2, Q)                                                     \
        {                                                                      \
            float4 w8q = *(const float4*)&W8s[w8base + (Q) * 4];               \
            float xs1_[4] = {X1.x, X1.y, X1.z, X1.w};                          \
            float xs2_[4] = {X2.x, X2.y, X2.z, X2.w};                          \
            float w8_[4] = {w8q.x, w8q.y, w8q.z, w8q.w};                       \
            _Pragma("unroll") for (int j = 0; j < 4; j++) {                    \
                int row = (Q) * 4 + j;                                         \
                const float4* wr = (const float4*)&Ws[wbase + row * 8];        \
                float4 w0 = wr[0];                                             \
                float4 w1 = wr[1];                                             \
                float xs1 = xs1_[j], xs2 = xs2_[j], w8 = w8_[j];               \
                acc1[0] = fmaf(xs1, w0.x, acc1[0]);                            \
                acc2[0] = fmaf(xs2, w0.x, acc2[0]);                            \
                acc1[1] = fmaf(xs1, w0.y, acc1[1]);                            \
                acc2[1] = fmaf(xs2, w0.y, acc2[1]);                            \
                acc1[2] = fmaf(xs1, w0.z, acc1[2]);                            \
                acc2[2] = fmaf(xs2, w0.z, acc2[2]);                            \
                acc1[3] = fmaf(xs1, w0.w, acc1[3]);                            \
                acc2[3] = fmaf(xs2, w0.w, acc2[3]);                            \
                acc1[4] = fmaf(xs1, w1.x, acc1[4]);                            \
                acc2[4] = fmaf(xs2, w1.x, acc2[4]);                            \
                acc1[5] = fmaf(xs1, w1.y, acc1[5]);                            \
                acc2[5] = fmaf(xs2, w1.y, acc2[5]);                            \
                acc1[6] = fmaf(xs1, w1.z, acc1[6]);                            \
                acc2[6] = fmaf(xs2, w1.z, acc2[6]);                            \
                acc1[7] = fmaf(xs1, w1.w, acc1[7]);                            \
                acc2[7] = fmaf(xs2, w1.w, acc2[7]);                            \
                acc1[8] = fmaf(xs1, w8, acc1[8]);                              \
                acc2[8] = fmaf(xs2, w8, acc2[8]);                              \
            }                                                                  \
        }

        A1 = xp1[0]; A2 = xp2[0];
#pragma unroll
        for (int q = 0; q < F4C; q += 2) {
            B1 = xp1[q + 1]; B2 = xp2[q + 1];
            CONSUME(A1, A2, q);
            if (q + 2 < F4C) { A1 = xp1[q + 2]; A2 = xp2[q + 2]; }
            CONSUME(B1, B2, q + 1);
        }
#undef CONSUME

        // reduce over the 8 chunk lanes (xor 1,2,4); all lanes end with full sums
#pragma unroll
        for (int o = 1; o <= 4; o <<= 1) {
#pragma unroll
            for (int l = 0; l < LL; l++) {
                acc1[l] += __shfl_xor_sync(0xffffffffu, acc1[l], o);
                acc2[l] += __shfl_xor_sync(0xffffffffu, acc2[l], o);
            }
        }

        // lane c==0 finalizes token1, lane c==1 finalizes token2
        bool doit = (c == 0) ? a1 : ((c == 1) ? a2 : false);
        if (doit) {
            float v[LL];
            int slot;
            if (c == 0) {
#pragma unroll
                for (int l = 0; l < LL; l++) v[l] = acc1[l] + Bs[l];
                slot = b1 * SS + d1;
            } else {
#pragma unroll
                for (int l = 0; l < LL; l++) v[l] = acc2[l] + Bs[l];
                slot = b2 * SS + d2;
            }
            float m = v[0];
#pragma unroll
            for (int l = 1; l < LL; l++) m = fmaxf(m, v[l]);
            float sum = 0.f;
#pragma unroll
            for (int l = 0; l < LL; l++) { v[l] = __expf(v[l] - m); sum += v[l]; }
            float r = 1.f / sum;
            float* op = out + (size_t)slot * LL;
#pragma unroll
            for (int l = 0; l < LL; l++) op[l] = v[l] * r;
        }
    }
}

// ---------------------------------------------------------------------------
extern "C" void kernel_launch(void* const* d_in, const int* in_sizes, int n_in,
                              void* d_out, int out_size) {
    const float* seq  = (const float*)d_in[0];   // [64,512,768] f32
    const int*   mask = (const int*)d_in[1];     // [64,512] i32
    const float* W    = (const float*)d_in[2];   // [768,9] f32
    const float* bias = (const float*)d_in[3];   // [9] f32
    float* out = (float*)d_out;                  // [64,512,9] f32

    scan_fill_kernel<<<BB, SS>>>(mask, bias, out);
    build_kernel<<<BB, SS>>>();
    main_kernel<<<NBLK, 256>>>(seq, W, bias, out);
}

// round 12
// speedup vs baseline: 1.9624x; 1.1279x over previous
#include <cuda_runtime.h>
#include <cuda_bf16.h>
#include <math.h>

// Problem dims (fixed by dataset)
#define BB 64
#define SS 512
#define HH 768
#define LL 9

#define SPLIT 8                 // chunk lanes per token
#define HC (HH / SPLIT)         // 96 features per chunk
#define F4C (HC / 4)            // 24 float4 per chunk
#define WREG (HC * 8 + 4)       // 772 floats, mod 32 = 4 -> bank rotation
#define W8REG (HC + 4)          // 100 floats, mod 32 = 4

// Scratch (no device allocations allowed)
__device__ int g_cnt[BB];        // valid count per batch
__device__ int g_src[BB * SS];   // per-batch: src token index for dest d

// ---------------------------------------------------------------------------
// Kernel A: warp-per-batch ballot scan of valid_mask -> src map + counts.
// 64 warps total (2 blocks x 1024 threads). ~16 ballot rounds per warp.
// ---------------------------------------------------------------------------
__global__ __launch_bounds__(1024) void scan_kernel(const int* __restrict__ mask) {
    int warp = (blockIdx.x * 1024 + threadIdx.x) >> 5;   // 0..63 = batch
    int lane = threadIdx.x & 31;
    if (warp >= BB) return;
    const int* mrow = mask + warp * SS;
    int base = 0;
#pragma unroll
    for (int it = 0; it < SS / 32; it++) {
        int s = it * 32 + lane;
        int m = (mrow[s] == 1) ? 1 : 0;
        unsigned bits = __ballot_sync(0xffffffffu, m);
        if (m) g_src[warp * SS + base + __popc(bits & ((1u << lane) - 1u))] = s;
        base += __popc(bits);
    }
    if (lane == 0) g_cnt[warp] = base;
}

// ---------------------------------------------------------------------------
// Kernel B: everything else.
//  - preamble: W -> smem (bank-rotated regions), prefix over g_cnt (warp scan)
//  - per-warp item mapping: lanes 0..7 binary-search the prefix, results
//    staged through SMEM (breaks register liveness into the GEMV loop)
//  - GEMV core: identical to round-10 (8 chunk-lanes x 4 token-lanes,
//    2 tokens/lane sharing W LDS loads, double-buffered x stages)
//  - tail fill: invalid dest slots <- softmax(bias) constant (disjoint slots,
//    so no ordering constraint vs the GEMV writes)
// ---------------------------------------------------------------------------
#define NBLK 296

__global__ __launch_bounds__(256, 2) void main_kernel(const float* __restrict__ seq,
                                                      const float* __restrict__ W,
                                                      const float* __restrict__ bias,
                                                      float* __restrict__ out) {
    __shared__ float Ws[SPLIT * WREG];    // cols 0..7, 8 floats/row  (~24.7 KB)
    __shared__ float W8s[SPLIT * W8REG];  // col 8, quad-packed       (~3.2 KB)
    __shared__ float Bs[LL];
    __shared__ int praw[BB];
    __shared__ int pref[BB + 1];          // pref[b] = sum cnt[0..b-1]; pref[BB]=total
    __shared__ int sitem[8][8];           // per-warp staged items

    int tid = threadIdx.x;
    if (tid < LL) Bs[tid] = bias[tid];
    if (tid < BB) praw[tid] = g_cnt[tid];
    for (int i = tid; i < SPLIT * WREG; i += 256) {
        int c = i / WREG, r = i % WREG;
        float val = 0.f;
        if (r < HC * 8) {
            int j = r / 8, col = r % 8;
            val = W[(c * HC + j) * LL + col];
        }
        Ws[i] = val;
    }
    for (int i = tid; i < SPLIT * W8REG; i += 256) {
        int c = i / W8REG, r = i % W8REG;
        float val = 0.f;
        if (r < HC) val = W[(c * HC + r) * LL + 8];
        W8s[i] = val;
    }
    __syncthreads();

    // warp-parallel exclusive prefix over 64 counts (warp 0 only)
    if (tid < 32) {
        int v0 = praw[tid];
        int v1 = praw[32 + tid];
#pragma unroll
        for (int o = 1; o < 32; o <<= 1) {
            int t0 = __shfl_up_sync(0xffffffffu, v0, o);
            int t1 = __shfl_up_sync(0xffffffffu, v1, o);
            if (tid >= o) { v0 += t0; v1 += t1; }
        }
        int sum0 = __shfl_sync(0xffffffffu, v0, 31);
        v1 += sum0;
        pref[tid + 1] = v0;
        pref[tid + 33] = v1;
        if (tid == 0) pref[0] = 0;
    }
    __syncthreads();

    int total = pref[BB];
    int n_sg = (total + 7) >> 3;   // supergroups of 8 work items

    int wid = tid >> 5, lane = tid & 31;
    int t_in = lane >> 3;   // token-lane 0..3
    int c    = lane & 7;    // chunk 0..7
    int wbase  = c * WREG;
    int w8base = c * W8REG;

    int warp_g = blockIdx.x * 8 + wid;
    int nwarps = NBLK * 8;

    for (int sg = warp_g; sg < n_sg; sg += nwarps) {
        // ---- item mapping: lanes 0..7 search; results via smem ----
        int ii = sg * 8 + lane;
        if (lane < 8) {
            int q = (ii < total) ? ii : (total - 1);
            int b = 0;
#pragma unroll
            for (int st = 32; st >= 1; st >>= 1) {
                int mb = b + st;
                if (mb <= BB - 1 && pref[mb] <= q) b = mb;
            }
            int d = q - pref[b];
            int s = g_src[b * SS + d];
            sitem[wid][lane] = (b << 18) | (d << 9) | s;
        }
        __syncwarp();

        int i1 = sg * 8 + t_in;
        int i2 = i1 + 4;
        bool a1 = i1 < total;
        bool a2 = i2 < total;
        int item1 = sitem[wid][t_in];
        int item2 = sitem[wid][t_in + 4];
        int b1 = item1 >> 18, d1 = (item1 >> 9) & 511, s1 = item1 & 511;
        int b2 = item2 >> 18, d2 = (item2 >> 9) & 511, s2 = item2 & 511;

        const float4* xp1 = (const float4*)(seq + (size_t)(b1 * SS + s1) * HH) + c * F4C;
        const float4* xp2 = (const float4*)(seq + (size_t)(b2 * SS + s2) * HH) + c * F4C;

        float acc1[LL], acc2[LL];
#pragma unroll
        for (int l = 0; l < LL; l++) { acc1[l] = 0.f; acc2[l] = 0.f; }

        float4 A1, A2, B1, B2;

#define CONSUME(X1, X2, Q)                                                     \
        {                                                                      \
            float4 w8q = *(const float4*)&W8s[w8base + (Q) * 4];               \
            float xs1_[4] = {X1.x, X1.y, X1.z, X1.w};                          \
            float xs2_[4] = {X2.x, X2.y, X2.z, X2.w};                          \
            float w8_[4] = {w8q.x, w8q.y, w8q.z, w8q.w};                       \
            _Pragma("unroll") for (int j = 0; j < 4; j++) {                    \
                int row = (Q) * 4 + j;                                         \
                const float4* wr = (const float4*)&Ws[wbase + row * 8];        \
                float4 w0 = wr[0];                                             \
                float4 w1 = wr[1];                                             \
                float xs1 = xs1_[j], xs2 = xs2_[j], w8 = w8_[j];               \
                acc1[0] = fmaf(xs1, w0.x, acc1[0]);                            \
                acc2[0] = fmaf(xs2, w0.x, acc2[0]);                            \
                acc1[1] = fmaf(xs1, w0.y, acc1[1]);                            \
                acc2[1] = fmaf(xs2, w0.y, acc2[1]);                            \
                acc1[2] = fmaf(xs1, w0.z, acc1[2]);                            \
                acc2[2] = fmaf(xs2, w0.z, acc2[2]);                            \
                acc1[3] = fmaf(xs1, w0.w, acc1[3]);                            \
                acc2[3] = fmaf(xs2, w0.w, acc2[3]);                            \
                acc1[4] = fmaf(xs1, w1.x, acc1[4]);                            \
                acc2[4] = fmaf(xs2, w1.x, acc2[4]);                            \
                acc1[5] = fmaf(xs1, w1.y, acc1[5]);                            \
                acc2[5] = fmaf(xs2, w1.y, acc2[5]);                            \
                acc1[6] = fmaf(xs1, w1.z, acc1[6]);                            \
                acc2[6] = fmaf(xs2, w1.z, acc2[6]);                            \
                acc1[7] = fmaf(xs1, w1.w, acc1[7]);                            \
                acc2[7] = fmaf(xs2, w1.w, acc2[7]);                            \
                acc1[8] = fmaf(xs1, w8, acc1[8]);                              \
                acc2[8] = fmaf(xs2, w8, acc2[8]);                              \
            }                                                                  \
        }

        A1 = xp1[0]; A2 = xp2[0];
#pragma unroll
        for (int q = 0; q < F4C; q += 2) {
            B1 = xp1[q + 1]; B2 = xp2[q + 1];
            CONSUME(A1, A2, q);
            if (q + 2 < F4C) { A1 = xp1[q + 2]; A2 = xp2[q + 2]; }
            CONSUME(B1, B2, q + 1);
        }
#undef CONSUME

        // reduce over the 8 chunk lanes (xor 1,2,4)
#pragma unroll
        for (int o = 1; o <= 4; o <<= 1) {
#pragma unroll
            for (int l = 0; l < LL; l++) {
                acc1[l] += __shfl_xor_sync(0xffffffffu, acc1[l], o);
                acc2[l] += __shfl_xor_sync(0xffffffffu, acc2[l], o);
            }
        }

        bool doit = (c == 0) ? a1 : ((c == 1) ? a2 : false);
        if (doit) {
            float v[LL];
            int slot;
            if (c == 0) {
#pragma unroll
                for (int l = 0; l < LL; l++) v[l] = acc1[l] + Bs[l];
                slot = b1 * SS + d1;
            } else {
#pragma unroll
                for (int l = 0; l < LL; l++) v[l] = acc2[l] + Bs[l];
                slot = b2 * SS + d2;
            }
            float m = v[0];
#pragma unroll
            for (int l = 1; l < LL; l++) m = fmaxf(m, v[l]);
            float sum = 0.f;
#pragma unroll
            for (int l = 0; l < LL; l++) { v[l] = __expf(v[l] - m); sum += v[l]; }
            float r = 1.f / sum;
            float* op = out + (size_t)slot * LL;
#pragma unroll
            for (int l = 0; l < LL; l++) op[l] = v[l] * r;
        }
        __syncwarp();   // protect sitem before a (rare) second iteration
    }

    // ---- tail fill: invalid dest slots get softmax(bias) constant ----
    int n_tail = BB * SS - total;
    if (n_tail > 0) {
        float bv[LL];
#pragma unroll
        for (int l = 0; l < LL; l++) bv[l] = Bs[l];
        float mx = bv[0];
#pragma unroll
        for (int l = 1; l < LL; l++) mx = fmaxf(mx, bv[l]);
        float sum = 0.f;
#pragma unroll
        for (int l = 0; l < LL; l++) { bv[l] = __expf(bv[l] - mx); sum += bv[l]; }
        float r = 1.f / sum;
#pragma unroll
        for (int l = 0; l < LL; l++) bv[l] *= r;

        int gtid = blockIdx.x * 256 + tid;
        int gsz = NBLK * 256;
        for (int j = gtid; j < n_tail; j += gsz) {
            // largest b with tpref(b) = b*SS - pref[b] <= j
            int b = 0;
#pragma unroll
            for (int st = 32; st >= 1; st >>= 1) {
                int m = b + st;
                if (m <= BB - 1 && (m * SS - pref[m]) <= j) b = m;
            }
            int d = (pref[b + 1] - pref[b]) + (j - (b * SS - pref[b]));
            float* op = out + (size_t)(b * SS + d) * LL;
#pragma unroll
            for (int l = 0; l < LL; l++) op[l] = bv[l];
        }
    }
}

// ---------------------------------------------------------------------------
extern "C" void kernel_launch(void* const* d_in, const int* in_sizes, int n_in,
                              void* d_out, int out_size) {
    const float* seq  = (const float*)d_in[0];   // [64,512,768] f32
    const int*   mask = (const int*)d_in[1];     // [64,512] i32
    const float* W    = (const float*)d_in[2];   // [768,9] f32
    const float* bias = (const float*)d_in[3];   // [9] f32
    float* out = (float*)d_out;                  // [64,512,9] f32

    scan_kernel<<<2, 1024>>>(mask);
    main_kernel<<<NBLK, 256>>>(seq, W, bias, out);
}

// round 13
// speedup vs baseline: 2.9024x; 1.4790x over previous
#include <cuda_runtime.h>
#include <cuda_bf16.h>
#include <math.h>

// Problem dims (fixed by dataset)
#define BB 64
#define SS 512
#define HH 768
#define LL 9

#define SPLIT 8                 // chunk lanes per token
#define HC (HH / SPLIT)         // 96 features per chunk
#define NQ (HH / 32)            // 24 stages (32 features each, 4 per chunk-lane)
#define WREG (HC * 8 + 4)       // 772 floats, mod 32 = 4 -> bank rotation
#define W8REG (HC + 4)          // 100 floats, mod 32 = 4

// Chunk c owns global rows { q*32 + c*4 + j : q in [0,24), j in [0,4) }.
// At stage q the 8 chunk lanes read float4 indices q*8+c -> one 128B line
// per token per stage (coalesced LDG, nL=4 per LDG.128 instead of ~32).

// Scratch (no device allocations allowed)
__device__ int g_cnt[BB];        // valid count per batch
__device__ int g_src[BB * SS];   // per-batch: src token index for dest d

// ---------------------------------------------------------------------------
// Kernel A: warp-per-batch ballot scan of valid_mask -> src map + counts.
// ---------------------------------------------------------------------------
__global__ __launch_bounds__(1024) void scan_kernel(const int* __restrict__ mask) {
    int warp = (blockIdx.x * 1024 + threadIdx.x) >> 5;   // 0..63 = batch
    int lane = threadIdx.x & 31;
    if (warp >= BB) return;
    const int* mrow = mask + warp * SS;
    int base = 0;
#pragma unroll
    for (int it = 0; it < SS / 32; it++) {
        int s = it * 32 + lane;
        int m = (mrow[s] == 1) ? 1 : 0;
        unsigned bits = __ballot_sync(0xffffffffu, m);
        if (m) g_src[warp * SS + base + __popc(bits & ((1u << lane) - 1u))] = s;
        base += __popc(bits);
    }
    if (lane == 0) g_cnt[warp] = base;
}

// ---------------------------------------------------------------------------
// Kernel B: main compute + item mapping + tail fill.
// GEMV core: 8 chunk-lanes x 4 token-lanes, 2 tokens/lane sharing W LDS.
// Chunk->feature mapping interleaved for coalesced x loads (see above).
// ---------------------------------------------------------------------------
#define NBLK 296

__global__ __launch_bounds__(256, 2) void main_kernel(const float* __restrict__ seq,
                                                      const float* __restrict__ W,
                                                      const float* __restrict__ bias,
                                                      float* __restrict__ out) {
    __shared__ float Ws[SPLIT * WREG];    // cols 0..7, 8 floats/row  (~24.7 KB)
    __shared__ float W8s[SPLIT * W8REG];  // col 8, quad-packed       (~3.2 KB)
    __shared__ float Bs[LL];
    __shared__ int praw[BB];
    __shared__ int pref[BB + 1];          // pref[b] = sum cnt[0..b-1]; pref[BB]=total
    __shared__ int sitem[8][8];           // per-warp staged items

    int tid = threadIdx.x;
    if (tid < LL) Bs[tid] = bias[tid];
    if (tid < BB) praw[tid] = g_cnt[tid];
    // W preamble with interleaved row permutation:
    // region c, local row j -> global row g = (j>>2)*32 + c*4 + (j&3)
    for (int i = tid; i < SPLIT * WREG; i += 256) {
        int c = i / WREG, r = i % WREG;
        float val = 0.f;
        if (r < HC * 8) {
            int j = r / 8, col = r % 8;
            int g = ((j >> 2) << 5) + (c << 2) + (j & 3);
            val = W[g * LL + col];
        }
        Ws[i] = val;
    }
    for (int i = tid; i < SPLIT * W8REG; i += 256) {
        int c = i / W8REG, r = i % W8REG;
        float val = 0.f;
        if (r < HC) {
            int g = ((r >> 2) << 5) + (c << 2) + (r & 3);
            val = W[g * LL + 8];
        }
        W8s[i] = val;
    }
    __syncthreads();

    // warp-parallel exclusive prefix over 64 counts (warp 0 only)
    if (tid < 32) {
        int v0 = praw[tid];
        int v1 = praw[32 + tid];
#pragma unroll
        for (int o = 1; o < 32; o <<= 1) {
            int t0 = __shfl_up_sync(0xffffffffu, v0, o);
            int t1 = __shfl_up_sync(0xffffffffu, v1, o);
            if (tid >= o) { v0 += t0; v1 += t1; }
        }
        int sum0 = __shfl_sync(0xffffffffu, v0, 31);
        v1 += sum0;
        pref[tid + 1] = v0;
        pref[tid + 33] = v1;
        if (tid == 0) pref[0] = 0;
    }
    __syncthreads();

    int total = pref[BB];
    int n_sg = (total + 7) >> 3;   // supergroups of 8 work items

    int wid = tid >> 5, lane = tid & 31;
    int t_in = lane >> 3;   // token-lane 0..3
    int c    = lane & 7;    // chunk 0..7
    int wbase  = c * WREG;
    int w8base = c * W8REG;

    int warp_g = blockIdx.x * 8 + wid;
    int nwarps = NBLK * 8;

    for (int sg = warp_g; sg < n_sg; sg += nwarps) {
        // ---- item mapping: lanes 0..7 search; results via smem ----
        int ii = sg * 8 + lane;
        if (lane < 8) {
            int q = (ii < total) ? ii : (total - 1);
            int b = 0;
#pragma unroll
            for (int st = 32; st >= 1; st >>= 1) {
                int mb = b + st;
                if (mb <= BB - 1 && pref[mb] <= q) b = mb;
            }
            int d = q - pref[b];
            int s = g_src[b * SS + d];
            sitem[wid][lane] = (b << 18) | (d << 9) | s;
        }
        __syncwarp();

        int i1 = sg * 8 + t_in;
        int i2 = i1 + 4;
        bool a1 = i1 < total;
        bool a2 = i2 < total;
        int item1 = sitem[wid][t_in];
        int item2 = sitem[wid][t_in + 4];
        int b1 = item1 >> 18, d1 = (item1 >> 9) & 511, s1 = item1 & 511;
        int b2 = item2 >> 18, d2 = (item2 >> 9) & 511, s2 = item2 & 511;

        // base row pointers (no chunk offset: chunk selects within each stage)
        const float4* xp1 = (const float4*)(seq + (size_t)(b1 * SS + s1) * HH);
        const float4* xp2 = (const float4*)(seq + (size_t)(b2 * SS + s2) * HH);

        float acc1[LL], acc2[LL];
#pragma unroll
        for (int l = 0; l < LL; l++) { acc1[l] = 0.f; acc2[l] = 0.f; }

        float4 A1, A2, B1, B2;

#define CONSUME(X1, X2, Q)                                                     \
        {                                                                      \
            float4 w8q = *(const float4*)&W8s[w8base + (Q) * 4];               \
            float xs1_[4] = {X1.x, X1.y, X1.z, X1.w};                          \
            float xs2_[4] = {X2.x, X2.y, X2.z, X2.w};                          \
            float w8_[4] = {w8q.x, w8q.y, w8q.z, w8q.w};                       \
            _Pragma("unroll") for (int j = 0; j < 4; j++) {                    \
                int row = (Q) * 4 + j;                                         \
                const float4* wr = (const float4*)&Ws[wbase + row * 8];        \
                float4 w0 = wr[0];                                             \
                float4 w1 = wr[1];                                             \
                float xs1 = xs1_[j], xs2 = xs2_[j], w8 = w8_[j];               \
                acc1[0] = fmaf(xs1, w0.x, acc1[0]);                            \
                acc2[0] = fmaf(xs2, w0.x, acc2[0]);                            \
                acc1[1] = fmaf(xs1, w0.y, acc1[1]);                            \
                acc2[1] = fmaf(xs2, w0.y, acc2[1]);                            \
                acc1[2] = fmaf(xs1, w0.z, acc1[2]);                            \
                acc2[2] = fmaf(xs2, w0.z, acc2[2]);                            \
                acc1[3] = fmaf(xs1, w0.w, acc1[3]);                            \
                acc2[3] = fmaf(xs2, w0.w, acc2[3]);                            \
                acc1[4] = fmaf(xs1, w1.x, acc1[4]);                            \
                acc2[4] = fmaf(xs2, w1.x, acc2[4]);                            \
                acc1[5] = fmaf(xs1, w1.y, acc1[5]);                            \
                acc2[5] = fmaf(xs2, w1.y, acc2[5]);                            \
                acc1[6] = fmaf(xs1, w1.z, acc1[6]);                            \
                acc2[6] = fmaf(xs2, w1.z, acc2[6]);                            \
                acc1[7] = fmaf(xs1, w1.w, acc1[7]);                            \
                acc2[7] = fmaf(xs2, w1.w, acc2[7]);                            \
                acc1[8] = fmaf(xs1, w8, acc1[8]);                              \
                acc2[8] = fmaf(xs2, w8, acc2[8]);                              \
            }                                                                  \
        }

        // stage q: this lane reads float4 index q*8 + c (coalesced per token)
        A1 = xp1[c]; A2 = xp2[c];
#pragma unroll
        for (int q = 0; q < NQ; q += 2) {
            B1 = xp1[(q + 1) * 8 + c]; B2 = xp2[(q + 1) * 8 + c];
            CONSUME(A1, A2, q);
            if (q + 2 < NQ) { A1 = xp1[(q + 2) * 8 + c]; A2 = xp2[(q + 2) * 8 + c]; }
            CONSUME(B1, B2, q + 1);
        }
#undef CONSUME

        // reduce over the 8 chunk lanes (xor 1,2,4)
#pragma unroll
        for (int o = 1; o <= 4; o <<= 1) {
#pragma unroll
            for (int l = 0; l < LL; l++) {
                acc1[l] += __shfl_xor_sync(0xffffffffu, acc1[l], o);
                acc2[l] += __shfl_xor_sync(0xffffffffu, acc2[l], o);
            }
        }

        bool doit = (c == 0) ? a1 : ((c == 1) ? a2 : false);
        if (doit) {
            float v[LL];
            int slot;
            if (c == 0) {
#pragma unroll
                for (int l = 0; l < LL; l++) v[l] = acc1[l] + Bs[l];
                slot = b1 * SS + d1;
            } else {
#pragma unroll
                for (int l = 0; l < LL; l++) v[l] = acc2[l] + Bs[l];
                slot = b2 * SS + d2;
            }
            float m = v[0];
#pragma unroll
            for (int l = 1; l < LL; l++) m = fmaxf(m, v[l]);
            float sum = 0.f;
#pragma unroll
            for (int l = 0; l < LL; l++) { v[l] = __expf(v[l] - m); sum += v[l]; }
            float r = 1.f / sum;
            float* op = out + (size_t)slot * LL;
#pragma unroll
            for (int l = 0; l < LL; l++) op[l] = v[l] * r;
        }
        __syncwarp();   // protect sitem before next iteration
    }

    // ---- tail fill: invalid dest slots get softmax(bias) constant ----
    int n_tail = BB * SS - total;
    if (n_tail > 0) {
        float bv[LL];
#pragma unroll
        for (int l = 0; l < LL; l++) bv[l] = Bs[l];
        float mx = bv[0];
#pragma unroll
        for (int l = 1; l < LL; l++) mx = fmaxf(mx, bv[l]);
        float sum = 0.f;
#pragma unroll
        for (int l = 0; l < LL; l++) { bv[l] = __expf(bv[l] - mx); sum += bv[l]; }
        float r = 1.f / sum;
#pragma unroll
        for (int l = 0; l < LL; l++) bv[l] *= r;

        int gtid = blockIdx.x * 256 + tid;
        int gsz = NBLK * 256;
        for (int j = gtid; j < n_tail; j += gsz) {
            // largest b with tpref(b) = b*SS - pref[b] <= j
            int b = 0;
#pragma unroll
            for (int st = 32; st >= 1; st >>= 1) {
                int m = b + st;
                if (m <= BB - 1 && (m * SS - pref[m]) <= j) b = m;
            }
            int d = (pref[b + 1] - pref[b]) + (j - (b * SS - pref[b]));
            float* op = out + (size_t)(b * SS + d) * LL;
#pragma unroll
            for (int l = 0; l < LL; l++) op[l] = bv[l];
        }
    }
}

// ---------------------------------------------------------------------------
extern "C" void kernel_launch(void* const* d_in, const int* in_sizes, int n_in,
                              void* d_out, int out_size) {
    const float* seq  = (const float*)d_in[0];   // [64,512,768] f32
    const int*   mask = (const int*)d_in[1];     // [64,512] i32
    const float* W    = (const float*)d_in[2];   // [768,9] f32
    const float* bias = (const float*)d_in[3];   // [9] f32
    float* out = (float*)d_out;                  // [64,512,9] f32

    scan_kernel<<<2, 1024>>>(mask);
    main_kernel<<<NBLK, 256>>>(seq, W, bias, out);
}